// round 15
// baseline (speedup 1.0000x reference)
#include <cuda_runtime.h>
#include <cuda_fp16.h>
#include <cuda_bf16.h>
#include <cstdint>
#include <cub/cub.cuh>

// ---------------- problem constants ----------------
#define HH 200
#define WW 200
#define NPIX (HH * WW)          // 40000
#define NANCH 360000            // HH*WW*9
#define PRE_NMS 6000
#define POST_NMS 300
#define NBLK 94                 // ceil(6000/64)
#define CLS_OFF 0
#define LOC_OFF 720000
#define ROI_OFF 2160000

#define ASTR 40                 // smem row stride in halves (32 + 8 pad)
#define HROWS 180               // 10 x 18 halo rows
#define PLANE_H (HROWS * ASTR)  // halves per A plane
#define BROWS 128

// ---------------- scratch (static device allocations) ----------------
__device__ float g_x[512 * NPIX];                 // relu(conv1) output, [oc][px]
__device__ __half g_ah[(size_t)NPIX * 512];       // features transposed [px][ic], high half
__device__ __half g_am[(size_t)NPIX * 512];       // low half
__device__ __half g_wh[(size_t)9 * 512 * 512];    // weights [tap][oc][ic], high half (x1024)
__device__ __half g_wm[(size_t)9 * 512 * 512];    // low half (x1024)
__device__ float g_boxes[NANCH * 4];
__device__ float g_score[NANCH];
__device__ unsigned int g_keys32[NANCH];
__device__ unsigned int g_vals32[NANCH];
__device__ unsigned int g_keys32_s[NANCH];
__device__ unsigned int g_vals32_s[NANCH];
__device__ float g_top[PRE_NMS * 4];
__device__ unsigned int g_validw32[192];          // validity bitmask (6144 bits)
__device__ unsigned long long g_mask[(size_t)PRE_NMS * NBLK];
__device__ unsigned char g_cub_temp[64u << 20];

// ---------------- small PTX helpers ----------------
__device__ __forceinline__ unsigned int smem_u32(const void* p) {
  unsigned int a;
  asm("{ .reg .u64 t; cvta.to.shared.u64 t, %1; cvt.u32.u64 %0, t; }" : "=r"(a) : "l"(p));
  return a;
}
__device__ __forceinline__ void cp_async16(unsigned int saddr, const void* gptr,
                                           unsigned int srcsize) {
  asm volatile("cp.async.cg.shared.global [%0], [%1], 16, %2;"
               :: "r"(saddr), "l"(gptr), "r"(srcsize));
}
__device__ __forceinline__ void ldmatrix_x4(unsigned int& r0, unsigned int& r1,
                                            unsigned int& r2, unsigned int& r3,
                                            unsigned int addr) {
  asm volatile("ldmatrix.sync.aligned.m8n8.x4.shared.b16 {%0,%1,%2,%3}, [%4];"
               : "=r"(r0), "=r"(r1), "=r"(r2), "=r"(r3) : "r"(addr));
}
__device__ __forceinline__ void mma_16816(float* c, const unsigned int* a,
                                          const unsigned int* b) {
  asm volatile(
      "mma.sync.aligned.m16n8k16.row.col.f32.f16.f16.f32 "
      "{%0,%1,%2,%3}, {%4,%5,%6,%7}, {%8,%9}, {%0,%1,%2,%3};"
      : "+f"(c[0]), "+f"(c[1]), "+f"(c[2]), "+f"(c[3])
      : "r"(a[0]), "r"(a[1]), "r"(a[2]), "r"(a[3]), "r"(b[0]), "r"(b[1]));
}

// ---------------- pre: transpose + fp16-split features (paired-ic 4B stores) ----------------
__global__ __launch_bounds__(256) void split_feat_kernel(const float* __restrict__ feat) {
  __shared__ float tile[32][33];
  const int tx = threadIdx.x;
  const int ty = threadIdx.y;
  const int tid = ty * 32 + tx;
  const int pxb = blockIdx.x * 32;
  const int icb = blockIdx.y * 32;
#pragma unroll
  for (int r = 0; r < 4; r++)
    tile[ty + r * 8][tx] = feat[(size_t)(icb + ty + r * 8) * NPIX + pxb + tx];
  __syncthreads();
#pragma unroll
  for (int it = 0; it < 2; it++) {
    const int item = it * 256 + tid;
    const int p = item & 15;          // ic pair index
    const int pxl = item >> 4;        // px row 0..31
    const float v0 = tile[2 * p][pxl];
    const float v1 = tile[2 * p + 1][pxl];
    const __half h0 = __float2half(v0);
    const __half m0 = __float2half(v0 - __half2float(h0));
    const __half h1 = __float2half(v1);
    const __half m1 = __float2half(v1 - __half2float(h1));
    const size_t base = ((size_t)(pxb + pxl) * 512 + icb + 2 * p) >> 1;
    ((unsigned int*)g_ah)[base] =
        (unsigned int)__half_as_ushort(h0) | ((unsigned int)__half_as_ushort(h1) << 16);
    ((unsigned int*)g_am)[base] =
        (unsigned int)__half_as_ushort(m0) | ((unsigned int)__half_as_ushort(m1) << 16);
  }
}

// ---------------- pre: split weights (scaled by 1024) ----------------
__global__ void split_w_kernel(const float* __restrict__ w1) {
  const int i = blockIdx.x * 256 + threadIdx.x;  // oc*512 + ic
  if (i >= 512 * 512) return;
#pragma unroll
  for (int t = 0; t < 9; t++) {
    const float w = w1[(size_t)i * 9 + t] * 1024.0f;
    const __half h = __float2half(w);
    const __half m = __float2half(w - __half2float(h));
    g_wh[(size_t)t * 262144 + i] = h;
    g_wm[(size_t)t * 262144 + i] = m;
  }
}

// ---------------- conv1 via mma.sync: spatial 16x8 px tile x 128 oc (R9/R6 config, FROZEN) ----------------
__global__ __launch_bounds__(256) void conv1_mma_kernel(const float* __restrict__ b1) {
  __shared__ __align__(16) __half Ah[2][PLANE_H];      // planes: 0=ah 1=am
  __shared__ __align__(16) __half Bsm[2][BROWS * ASTR];

  const int tid = threadIdx.x;
  const int lane = tid & 31;
  const int wid = tid >> 5;
  const int wm = wid & 1;          // px half (64 px)
  const int wn = wid >> 1;         // oc quarter (32 oc)

  const int oc0 = blockIdx.x * 128;
  const int x0 = blockIdx.y * 16;  // 13 x-tiles
  const int y0 = blockIdx.z * 8;   // 25 y-tiles

  const unsigned int aBase = smem_u32(Ah);
  const unsigned int bBase = smem_u32(Bsm);
  const unsigned int BUFB = BROWS * ASTR * 2;

  unsigned int hb[4];
#pragma unroll
  for (int mf = 0; mf < 4; mf++)
    hb[mf] = (unsigned)(((wm * 4 + mf) * 18 + (lane & 15)) * (ASTR * 2) + (lane >> 4) * 16);
  const unsigned int bfrag_off =
      (unsigned)((wn * 32 + (lane & 7)) * (ASTR * 2) + (lane >> 3) * 16);

  float acc[4][4][4];
#pragma unroll
  for (int mf = 0; mf < 4; mf++)
#pragma unroll
    for (int nf = 0; nf < 4; nf++)
#pragma unroll
      for (int q = 0; q < 4; q++) acc[mf][nf][q] = 0.f;

  auto load_A_halo = [&](int c) {
    for (int idx = tid; idx < 1440; idx += 256) {
      const int pl = idx / 720;
      const int rr = idx - pl * 720;
      const int hrow = rr >> 2;
      const int seg = rr & 3;
      const int hr = hrow / 18;
      const int hc = hrow - hr * 18;
      const int gy = y0 + hr - 1;
      const int gx = x0 + hc - 1;
      const bool ok = ((unsigned)gy < (unsigned)HH) && ((unsigned)gx < (unsigned)WW);
      const int gpx = ok ? (gy * WW + gx) : 0;
      const __half* src = (pl ? g_am : g_ah) + (size_t)gpx * 512 + c * 32 + seg * 8;
      cp_async16(aBase + (unsigned)(pl * PLANE_H * 2 + hrow * (ASTR * 2) + seg * 16),
                 src, ok ? 16u : 0u);
    }
  };
  auto load_B = [&](int c, int ph, int buf) {
    const int tap = ph >> 1;
    const int bsel = ph & 1;
    const __half* plane = (bsel ? g_wm : g_wh) + (size_t)tap * 262144;
    for (int idx = tid; idx < 512; idx += 256) {
      const int row = idx >> 2;
      const int seg = idx & 3;
      const __half* src = plane + (size_t)(oc0 + row) * 512 + c * 32 + seg * 8;
      cp_async16(bBase + (unsigned)(buf * BUFB + row * (ASTR * 2) + seg * 16), src,
                 16u);
    }
  };

  for (int c = 0; c < 16; c++) {
    load_A_halo(c);
    load_B(c, 0, 0);
    asm volatile("cp.async.commit_group;");
    asm volatile("cp.async.wait_group 0;");
    __syncthreads();

    for (int ph = 0; ph < 18; ph++) {
      const int buf = ph & 1;
      if (ph + 1 < 18) {
        load_B(c, ph + 1, buf ^ 1);
        asm volatile("cp.async.commit_group;");
        asm volatile("cp.async.wait_group 1;");
      } else {
        asm volatile("cp.async.wait_group 0;");
      }
      __syncthreads();

      const int tap = ph >> 1;
      const int bsel = ph & 1;
      const int dy = tap / 3;
      const int dxx = tap - dy * 3;
      const unsigned int tapoff = (unsigned)((dy * 18 + dxx) * (ASTR * 2));
      const unsigned int bb = bBase + buf * BUFB;

      unsigned int bf[4][4];
#pragma unroll
      for (int nf = 0; nf < 4; nf++)
        ldmatrix_x4(bf[nf][0], bf[nf][1], bf[nf][2], bf[nf][3],
                    bb + bfrag_off + (unsigned)(nf * 8 * (ASTR * 2)));

      const int npass = bsel ? 1 : 2;
#pragma unroll
      for (int pa = 0; pa < 2; pa++) {
        if (pa >= npass) break;
        const unsigned int ap = aBase + (unsigned)((bsel ? 0 : pa) * PLANE_H * 2) + tapoff;
#pragma unroll
        for (int ks = 0; ks < 2; ks++) {
          unsigned int a[4][4];
#pragma unroll
          for (int mf = 0; mf < 4; mf++)
            ldmatrix_x4(a[mf][0], a[mf][1], a[mf][2], a[mf][3],
                        ap + hb[mf] + (unsigned)(ks * 32));
#pragma unroll
          for (int mf = 0; mf < 4; mf++)
#pragma unroll
            for (int nf = 0; nf < 4; nf++) mma_16816(acc[mf][nf], a[mf], &bf[nf][ks * 2]);
        }
      }
      __syncthreads();
    }
  }

  // epilogue: acc/1024 + bias, relu -> g_x[oc][gy*200+gx]
  const float inv = 1.0f / 1024.0f;
#pragma unroll
  for (int mf = 0; mf < 4; mf++) {
    const int gy = y0 + wm * 4 + mf;
    const int c_lo = lane >> 2;
#pragma unroll
    for (int nf = 0; nf < 4; nf++) {
      const int ocb = oc0 + wn * 32 + nf * 8 + (lane & 3) * 2;
      const float bias0 = b1[ocb];
      const float bias1 = b1[ocb + 1];
      const int gxa = x0 + c_lo;
      const int gxb = gxa + 8;
      if (gxa < WW) {
        float v0 = acc[mf][nf][0] * inv + bias0;
        float v1 = acc[mf][nf][1] * inv + bias1;
        g_x[(size_t)ocb * NPIX + gy * WW + gxa] = v0 > 0.f ? v0 : 0.f;
        g_x[(size_t)(ocb + 1) * NPIX + gy * WW + gxa] = v1 > 0.f ? v1 : 0.f;
      }
      if (gxb < WW) {
        float v2 = acc[mf][nf][2] * inv + bias0;
        float v3 = acc[mf][nf][3] * inv + bias1;
        g_x[(size_t)ocb * NPIX + gy * WW + gxb] = v2 > 0.f ? v2 : 0.f;
        g_x[(size_t)(ocb + 1) * NPIX + gy * WW + gxb] = v3 > 0.f ? v3 : 0.f;
      }
    }
  }
}

// ---------------- head: fused 1x1 convs, 8-way oc split, 2 adjacent px per thread ----------------
// 1000 blocks for ~2x occupancy (LDG-latency-bound loop). Per ic: 1 float2 LDG
// + 2 broadcast float4 LDS feed 14 FFMA. Per-output ic-ascending accumulation
// order unchanged -> bit-identical results.
__global__ __launch_bounds__(160) void head_kernel(
    const float* __restrict__ wc, const float* __restrict__ bc,
    const float* __restrict__ wl, const float* __restrict__ bl,
    float* __restrict__ out) {
  __shared__ __align__(16) float Ws[512][8];   // 7 used, padded to 8 for float4
  const int tid = threadIdx.x;
  const int px0 = blockIdx.x * 320;
  const int obase = blockIdx.y * 7;   // 8 groups of 7 (54 outputs, last 2 slots unused)

  for (int idx = tid; idx < 512 * 8; idx += 160) {
    const int ic = idx >> 3;
    const int o = idx & 7;
    const int og = obase + o;
    float w = 0.f;
    if (o < 7 && og < 18) w = wc[og * 512 + ic];
    else if (o < 7 && og < 54) w = wl[(og - 18) * 512 + ic];
    Ws[ic][o] = w;
  }
  __syncthreads();

  const int pxA = px0 + 2 * tid;       // even, float2-aligned
  const int pxB = pxA + 1;
  float accA[7], accB[7];
#pragma unroll
  for (int o = 0; o < 7; o++) { accA[o] = 0.f; accB[o] = 0.f; }

#pragma unroll 4
  for (int ic = 0; ic < 512; ic++) {
    const float2 xv = *(const float2*)&g_x[(size_t)ic * NPIX + pxA];
    const float xa = xv.x;
    const float xb = xv.y;
    const float4* wrow = (const float4*)Ws[ic];
    const float4 w0 = wrow[0];
    const float4 w1 = wrow[1];
    accA[0] += w0.x * xa;  accA[1] += w0.y * xa;  accA[2] += w0.z * xa;  accA[3] += w0.w * xa;
    accA[4] += w1.x * xa;  accA[5] += w1.y * xa;  accA[6] += w1.z * xa;
    accB[0] += w0.x * xb;  accB[1] += w0.y * xb;  accB[2] += w0.z * xb;  accB[3] += w0.w * xb;
    accB[4] += w1.x * xb;  accB[5] += w1.y * xb;  accB[6] += w1.z * xb;
  }

#pragma unroll
  for (int o = 0; o < 7; o++) {
    const int og = obase + o;
    if (og < 18) {
      const int a = og >> 1, cc = og & 1;
      out[CLS_OFF + ((size_t)pxA * 9 + a) * 2 + cc] = accA[o] + bc[og];
      out[CLS_OFF + ((size_t)pxB * 9 + a) * 2 + cc] = accB[o] + bc[og];
    } else if (og < 54) {
      const int l = og - 18;
      const int a = l >> 2, cc = l & 3;
      out[LOC_OFF + ((size_t)pxA * 9 + a) * 4 + cc] = accA[o] + bl[l];
      out[LOC_OFF + ((size_t)pxB * 9 + a) * 4 + cc] = accB[o] + bl[l];
    }
  }
}

// ---------------- decode + score + sort key (vectorized loads/stores) ----------------
__global__ void decode_kernel(const float* __restrict__ anchor,
                              const float* __restrict__ out) {
  const int n = blockIdx.x * 256 + threadIdx.x;
  if (n >= NANCH) return;

  const float4 anc = ((const float4*)anchor)[n];
  const float ax1 = anc.x, ay1 = anc.y, ax2 = anc.z, ay2 = anc.w;
  const float acx = __fmul_rn(__fadd_rn(ax2, ax1), 0.5f);
  const float acy = __fmul_rn(__fadd_rn(ay2, ay1), 0.5f);
  const float aw = __fsub_rn(ax2, ax1);
  const float ah = __fsub_rn(ay2, ay1);

  const float4 locv = ((const float4*)(out + LOC_OFF))[n];
  const float l0 = locv.x, l1 = locv.y, l2 = locv.z, l3 = locv.w;

  const float cx = __fadd_rn(__fmul_rn(l0, aw), acx);
  const float cy = __fadd_rn(__fmul_rn(l1, ah), acy);
  const float w = __fmul_rn(expf(l2), aw);
  const float h = __fmul_rn(expf(l3), ah);

  float x1 = __fsub_rn(cx, __fmul_rn(w, 0.5f));
  float y1 = __fsub_rn(cy, __fmul_rn(h, 0.5f));
  float x2 = __fadd_rn(cx, __fmul_rn(w, 0.5f));
  float y2 = __fadd_rn(cy, __fmul_rn(h, 0.5f));
  x1 = fminf(fmaxf(x1, 0.f), 1.f);
  y1 = fminf(fmaxf(y1, 0.f), 1.f);
  x2 = fminf(fmaxf(x2, 0.f), 1.f);
  y2 = fminf(fmaxf(y2, 0.f), 1.f);

  float4 bx;
  bx.x = x1; bx.y = y1; bx.z = x2; bx.w = y2;
  ((float4*)g_boxes)[n] = bx;

  const float2 clsv = ((const float2*)(out + CLS_OFF))[n];
  float s = 1.f / (1.f + expf(__fsub_rn(clsv.x, clsv.y)));

  const float MINSZ = (float)(16.0 / 1000.0);
  const float ws = __fsub_rn(x2, x1);
  const float hs = __fsub_rn(y2, y1);
  const bool valid = (hs >= MINSZ) && (ws >= MINSZ);
  if (!valid) s = -1.0f;
  g_score[n] = s;

  unsigned int bits = __float_as_uint(s);
  unsigned int u = (bits & 0x80000000u) ? ~bits : (bits | 0x80000000u);
  // ascending radix sort of ~u -> descending score; CUB radix is stable, so
  // equal scores keep ascending index order (matches jax top_k tie rule).
  g_keys32[n] = ~u;
  g_vals32[n] = (unsigned int)n;
}

// ---------------- gather top 6000 + validity ballot (float4 copy) ----------------
__global__ void gather_kernel() {
  const int i = blockIdx.x * 256 + threadIdx.x;   // 24 blocks -> i < 6144
  int valid = 0;
  if (i < PRE_NMS) {
    const int idx = (int)g_vals32_s[i];
    ((float4*)g_top)[i] = ((const float4*)g_boxes)[idx];
    valid = (g_score[idx] >= 0.f) ? 1 : 0;
  }
  const unsigned int bal = __ballot_sync(0xffffffffu, valid);
  if ((threadIdx.x & 31) == 0) g_validw32[i >> 5] = bal;
}

// ---------------- NMS bitmask: paired column blocks (2 cb per block) ----------------
__global__ __launch_bounds__(64) void mask_kernel() {
  const int cb0 = blockIdx.x * 2;     // 47 x-blocks cover 94 cb
  const int rb = blockIdx.y;
  __shared__ float cbx[128][4];
  const int t = threadIdx.x;
#pragma unroll
  for (int half = 0; half < 2; half++) {
    const int jg = (cb0 + half) * 64 + t;
    if (jg < PRE_NMS) {
      const float4 b = ((const float4*)g_top)[jg];
      cbx[half * 64 + t][0] = b.x;
      cbx[half * 64 + t][1] = b.y;
      cbx[half * 64 + t][2] = b.z;
      cbx[half * 64 + t][3] = b.w;
    }
  }
  __syncthreads();
  const int i = rb * 64 + t;
  if (i >= PRE_NMS) return;

  const float4 bi = ((const float4*)g_top)[i];
  const float ix1 = bi.x, iy1 = bi.y, ix2 = bi.z, iy2 = bi.w;
  const float area_i = __fmul_rn(__fsub_rn(ix2, ix1), __fsub_rn(iy2, iy1));

#pragma unroll
  for (int half = 0; half < 2; half++) {
    const int cb = cb0 + half;
    unsigned long long bits = 0ull;
    const int jmax = min(64, PRE_NMS - cb * 64);
    for (int jj = 0; jj < jmax; jj++) {
      const int j = cb * 64 + jj;
      if (j <= i) continue;
      const int sj = half * 64 + jj;
      const float bx1 = cbx[sj][0], by1 = cbx[sj][1], bx2 = cbx[sj][2], by2 = cbx[sj][3];
      const float area_j = __fmul_rn(__fsub_rn(bx2, bx1), __fsub_rn(by2, by1));
      const float xx1 = fmaxf(ix1, bx1);
      const float yy1 = fmaxf(iy1, by1);
      const float xx2 = fminf(ix2, bx2);
      const float yy2 = fminf(iy2, by2);
      const float iw = fmaxf(__fsub_rn(xx2, xx1), 0.f);
      const float ih = fmaxf(__fsub_rn(yy2, yy1), 0.f);
      const float inter = __fmul_rn(iw, ih);
      const float denom = __fadd_rn(__fsub_rn(__fadd_rn(area_i, area_j), inter), 1e-12f);
      const float iou = inter / denom;
      if (iou > 0.7f) bits |= (1ull << jj);
    }
    g_mask[(size_t)i * NBLK + cb] = bits;
  }
}

// ---------------- sequential keep: word-at-a-time bit scan, early exit at 300 ----------------
__global__ void keep_kernel(float* __restrict__ out) {
  const int lane = threadIdx.x;
  unsigned long long r0 = 0ull, r1 = 0ull, r2 = 0ull;  // suppr words lane, +32, +64
  __shared__ unsigned long long validw[NBLK];
  __shared__ int kept_s[POST_NMS];

  for (int w = lane; w < NBLK; w += 32) {
    const unsigned int lo = g_validw32[2 * w];
    const unsigned int hi = (2 * w + 1 < 192) ? g_validw32[2 * w + 1] : 0u;
    validw[w] = (unsigned long long)lo | ((unsigned long long)hi << 32);
  }
  __syncwarp();

  int count = 0;
  for (int w = 0; w < NBLK && count < POST_NMS; w++) {
    const int slot = w >> 5;
    const int src = w & 31;
    unsigned long long v = (slot == 0) ? r0 : ((slot == 1) ? r1 : r2);
    unsigned long long sup = __shfl_sync(0xffffffffu, v, src);
    unsigned long long cand = validw[w] & ~sup;
    while (cand && count < POST_NMS) {
      const int b = __ffsll((long long)cand) - 1;
      const int i = w * 64 + b;
      if (lane == 0) kept_s[count] = i;
      count++;
      const unsigned long long* row = &g_mask[(size_t)i * NBLK];
      r0 |= row[lane];
      r1 |= row[lane + 32];
      if (lane + 64 < NBLK) r2 |= row[lane + 64];
      if (i + 1 < PRE_NMS) {
        const unsigned long long* nr = &g_mask[(size_t)(i + 1) * NBLK];
        asm volatile("prefetch.global.L1 [%0];" :: "l"(nr + lane));
        asm volatile("prefetch.global.L1 [%0];" :: "l"(nr + lane + 32));
      }
      if (i + 2 < PRE_NMS) {
        const unsigned long long* nr = &g_mask[(size_t)(i + 2) * NBLK];
        asm volatile("prefetch.global.L1 [%0];" :: "l"(nr + lane));
        asm volatile("prefetch.global.L1 [%0];" :: "l"(nr + lane + 32));
      }
      v = (slot == 0) ? r0 : ((slot == 1) ? r1 : r2);
      sup = __shfl_sync(0xffffffffu, v, src);
      const unsigned long long above = (b == 63) ? 0ull : (~0ull << (b + 1));
      cand = validw[w] & ~sup & above;
    }
  }
  __syncwarp();

  for (int k = lane; k < POST_NMS; k += 32) {
    float b0 = 0.f, b1v = 0.f, b2 = 0.f, b3 = 0.f;
    if (k < count) {
      const int i = kept_s[k];
      b0 = g_top[i * 4 + 0];
      b1v = g_top[i * 4 + 1];
      b2 = g_top[i * 4 + 2];
      b3 = g_top[i * 4 + 3];
    }
    out[ROI_OFF + k * 4 + 0] = b0;
    out[ROI_OFF + k * 4 + 1] = b1v;
    out[ROI_OFF + k * 4 + 2] = b2;
    out[ROI_OFF + k * 4 + 3] = b3;
  }
}

// ---------------- launch ----------------
extern "C" void kernel_launch(void* const* d_in, const int* in_sizes, int n_in,
                              void* d_out, int out_size) {
  const float* feat = (const float*)d_in[0];
  const float* anchor = (const float*)d_in[1];
  const float* w1 = (const float*)d_in[2];
  const float* b1 = (const float*)d_in[3];
  const float* wc = (const float*)d_in[4];
  const float* bc = (const float*)d_in[5];
  const float* wl = (const float*)d_in[6];
  const float* bl = (const float*)d_in[7];
  float* out = (float*)d_out;

  split_feat_kernel<<<dim3(1250, 16), dim3(32, 8)>>>(feat);
  split_w_kernel<<<(512 * 512 + 255) / 256, 256>>>(w1);
  conv1_mma_kernel<<<dim3(4, 13, 25), 256>>>(b1);

  head_kernel<<<dim3(125, 8), 160>>>(wc, bc, wl, bl, out);
  decode_kernel<<<(NANCH + 255) / 256, 256>>>(anchor, out);

  // CUB stable radix SortPairs on 32-bit keys
  void* d_temp = nullptr;
  unsigned int *dk, *dks, *dv, *dvs;
  cudaGetSymbolAddress(&d_temp, g_cub_temp);
  cudaGetSymbolAddress((void**)&dk, g_keys32);
  cudaGetSymbolAddress((void**)&dks, g_keys32_s);
  cudaGetSymbolAddress((void**)&dv, g_vals32);
  cudaGetSymbolAddress((void**)&dvs, g_vals32_s);
  size_t temp_bytes = 0;
  cub::DeviceRadixSort::SortPairs(nullptr, temp_bytes, dk, dks, dv, dvs, NANCH,
                                  0, 32, (cudaStream_t)0);
  if (temp_bytes > (size_t)(64u << 20)) temp_bytes = (size_t)(64u << 20);
  cub::DeviceRadixSort::SortPairs(d_temp, temp_bytes, dk, dks, dv, dvs, NANCH,
                                  0, 32, (cudaStream_t)0);

  gather_kernel<<<24, 256>>>();
  mask_kernel<<<dim3(47, NBLK), 64>>>();
  keep_kernel<<<1, 32>>>(out);
}

// round 16
// speedup vs baseline: 1.0291x; 1.0291x over previous
#include <cuda_runtime.h>
#include <cuda_fp16.h>
#include <cuda_bf16.h>
#include <cstdint>
#include <cub/cub.cuh>

// ---------------- problem constants ----------------
#define HH 200
#define WW 200
#define NPIX (HH * WW)          // 40000
#define NANCH 360000            // HH*WW*9
#define PRE_NMS 6000
#define POST_NMS 300
#define NBLK 94                 // ceil(6000/64)
#define CLS_OFF 0
#define LOC_OFF 720000
#define ROI_OFF 2160000

#define ASTR 40                 // smem row stride in halves (32 + 8 pad)
#define HROWS 180               // 10 x 18 halo rows
#define PLANE_H (HROWS * ASTR)  // halves per A plane (7200)
#define PLANE_B (PLANE_H * 2)   // bytes per A plane (14400)
#define ABUF_B (2 * PLANE_B)    // bytes per A buffer, both planes (28800)
#define BROWS 128
#define BBUF_B (BROWS * ASTR * 2)           // bytes per B buffer (10240)
#define CONV_SMEM (2 * ABUF_B + 2 * BBUF_B) // 78080 bytes dynamic smem

// ---------------- scratch (static device allocations) ----------------
__device__ float g_x[512 * NPIX];                 // relu(conv1) output, [oc][px]
__device__ __half g_ah[(size_t)NPIX * 512];       // features transposed [px][ic], high half
__device__ __half g_am[(size_t)NPIX * 512];       // low half
__device__ __half g_wh[(size_t)9 * 512 * 512];    // weights [tap][oc][ic], high half (x1024)
__device__ __half g_wm[(size_t)9 * 512 * 512];    // low half (x1024)
__device__ float g_boxes[NANCH * 4];
__device__ float g_score[NANCH];
__device__ unsigned int g_keys32[NANCH];
__device__ unsigned int g_vals32[NANCH];
__device__ unsigned int g_keys32_s[NANCH];
__device__ unsigned int g_vals32_s[NANCH];
__device__ float g_top[PRE_NMS * 4];
__device__ unsigned int g_validw32[192];          // validity bitmask (6144 bits)
__device__ unsigned long long g_mask[(size_t)PRE_NMS * NBLK];
__device__ unsigned char g_cub_temp[64u << 20];

// ---------------- small PTX helpers ----------------
__device__ __forceinline__ unsigned int smem_u32(const void* p) {
  unsigned int a;
  asm("{ .reg .u64 t; cvta.to.shared.u64 t, %1; cvt.u32.u64 %0, t; }" : "=r"(a) : "l"(p));
  return a;
}
__device__ __forceinline__ void cp_async16(unsigned int saddr, const void* gptr,
                                           unsigned int srcsize) {
  asm volatile("cp.async.cg.shared.global [%0], [%1], 16, %2;"
               :: "r"(saddr), "l"(gptr), "r"(srcsize));
}
__device__ __forceinline__ void ldmatrix_x4(unsigned int& r0, unsigned int& r1,
                                            unsigned int& r2, unsigned int& r3,
                                            unsigned int addr) {
  asm volatile("ldmatrix.sync.aligned.m8n8.x4.shared.b16 {%0,%1,%2,%3}, [%4];"
               : "=r"(r0), "=r"(r1), "=r"(r2), "=r"(r3) : "r"(addr));
}
__device__ __forceinline__ void mma_16816(float* c, const unsigned int* a,
                                          const unsigned int* b) {
  asm volatile(
      "mma.sync.aligned.m16n8k16.row.col.f32.f16.f16.f32 "
      "{%0,%1,%2,%3}, {%4,%5,%6,%7}, {%8,%9}, {%0,%1,%2,%3};"
      : "+f"(c[0]), "+f"(c[1]), "+f"(c[2]), "+f"(c[3])
      : "r"(a[0]), "r"(a[1]), "r"(a[2]), "r"(a[3]), "r"(b[0]), "r"(b[1]));
}

// ---------------- pre: transpose + fp16-split features (paired-ic 4B stores) ----------------
__global__ __launch_bounds__(256) void split_feat_kernel(const float* __restrict__ feat) {
  __shared__ float tile[32][33];
  const int tx = threadIdx.x;
  const int ty = threadIdx.y;
  const int tid = ty * 32 + tx;
  const int pxb = blockIdx.x * 32;
  const int icb = blockIdx.y * 32;
#pragma unroll
  for (int r = 0; r < 4; r++)
    tile[ty + r * 8][tx] = feat[(size_t)(icb + ty + r * 8) * NPIX + pxb + tx];
  __syncthreads();
#pragma unroll
  for (int it = 0; it < 2; it++) {
    const int item = it * 256 + tid;
    const int p = item & 15;          // ic pair index
    const int pxl = item >> 4;        // px row 0..31
    const float v0 = tile[2 * p][pxl];
    const float v1 = tile[2 * p + 1][pxl];
    const __half h0 = __float2half(v0);
    const __half m0 = __float2half(v0 - __half2float(h0));
    const __half h1 = __float2half(v1);
    const __half m1 = __float2half(v1 - __half2float(h1));
    const size_t base = ((size_t)(pxb + pxl) * 512 + icb + 2 * p) >> 1;
    ((unsigned int*)g_ah)[base] =
        (unsigned int)__half_as_ushort(h0) | ((unsigned int)__half_as_ushort(h1) << 16);
    ((unsigned int*)g_am)[base] =
        (unsigned int)__half_as_ushort(m0) | ((unsigned int)__half_as_ushort(m1) << 16);
  }
}

// ---------------- pre: split weights (scaled by 1024) ----------------
__global__ void split_w_kernel(const float* __restrict__ w1) {
  const int i = blockIdx.x * 256 + threadIdx.x;  // oc*512 + ic
  if (i >= 512 * 512) return;
#pragma unroll
  for (int t = 0; t < 9; t++) {
    const float w = w1[(size_t)i * 9 + t] * 1024.0f;
    const __half h = __float2half(w);
    const __half m = __float2half(w - __half2float(h));
    g_wh[(size_t)t * 262144 + i] = h;
    g_wm[(size_t)t * 262144 + i] = m;
  }
}

// ---------------- conv1 via mma.sync: spatial 16x8 px tile x 128 oc ----------------
// R9 mainloop (two syncs per phase, double-buffered B) PLUS A-halo double
// buffering: chunk c+1's halo is prefetched during chunk c phase 0, removing
// the 16 per-chunk full cp.async drains. Parity proof: A(c+1) targets buffer
// (c+1)&1, last read during chunk c-1 whose compute ended before the (c-1,17)
// trailing sync, which precedes the (c,0) issue. B parity continues across
// chunks (18 phases even -> buf stays ph&1). Math order unchanged.
__global__ __launch_bounds__(256) void conv1_mma_kernel(const float* __restrict__ b1) {
  extern __shared__ __align__(16) unsigned char dynsmem[];
  const unsigned int aBase = smem_u32(dynsmem);              // 2 abuf x 2 planes
  const unsigned int bBase = aBase + 2 * ABUF_B;             // 2 B buffers

  const int tid = threadIdx.x;
  const int lane = tid & 31;
  const int wid = tid >> 5;
  const int wm = wid & 1;          // px half (64 px)
  const int wn = wid >> 1;         // oc quarter (32 oc)

  const int oc0 = blockIdx.x * 128;
  const int x0 = blockIdx.y * 16;  // 13 x-tiles
  const int y0 = blockIdx.z * 8;   // 25 y-tiles

  unsigned int hb[4];
#pragma unroll
  for (int mf = 0; mf < 4; mf++)
    hb[mf] = (unsigned)(((wm * 4 + mf) * 18 + (lane & 15)) * (ASTR * 2) + (lane >> 4) * 16);
  const unsigned int bfrag_off =
      (unsigned)((wn * 32 + (lane & 7)) * (ASTR * 2) + (lane >> 3) * 16);

  float acc[4][4][4];
#pragma unroll
  for (int mf = 0; mf < 4; mf++)
#pragma unroll
    for (int nf = 0; nf < 4; nf++)
#pragma unroll
      for (int q = 0; q < 4; q++) acc[mf][nf][q] = 0.f;

  auto load_A_halo = [&](int c, int abuf) {
    for (int idx = tid; idx < 1440; idx += 256) {
      const int pl = idx / 720;
      const int rr = idx - pl * 720;
      const int hrow = rr >> 2;
      const int seg = rr & 3;
      const int hr = hrow / 18;
      const int hc = hrow - hr * 18;
      const int gy = y0 + hr - 1;
      const int gx = x0 + hc - 1;
      const bool ok = ((unsigned)gy < (unsigned)HH) && ((unsigned)gx < (unsigned)WW);
      const int gpx = ok ? (gy * WW + gx) : 0;
      const __half* src = (pl ? g_am : g_ah) + (size_t)gpx * 512 + c * 32 + seg * 8;
      cp_async16(aBase + (unsigned)(abuf * ABUF_B + pl * PLANE_B + hrow * (ASTR * 2) + seg * 16),
                 src, ok ? 16u : 0u);
    }
  };
  auto load_B = [&](int c, int ph, int buf) {
    const int tap = ph >> 1;
    const int bsel = ph & 1;
    const __half* plane = (bsel ? g_wm : g_wh) + (size_t)tap * 262144;
    for (int idx = tid; idx < 512; idx += 256) {
      const int row = idx >> 2;
      const int seg = idx & 3;
      const __half* src = plane + (size_t)(oc0 + row) * 512 + c * 32 + seg * 8;
      cp_async16(bBase + (unsigned)(buf * BBUF_B + row * (ASTR * 2) + seg * 16), src,
                 16u);
    }
  };

  // prologue: chunk 0 halo + first B tile, full drain once
  load_A_halo(0, 0);
  load_B(0, 0, 0);
  asm volatile("cp.async.commit_group;");
  asm volatile("cp.async.wait_group 0;");
  __syncthreads();

  for (int c = 0; c < 16; c++) {
    const int ab = c & 1;
    for (int ph = 0; ph < 18; ph++) {
      const int buf = ph & 1;
      const bool last = (c == 15) && (ph == 17);
      if (!last) {
        if (ph + 1 < 18) load_B(c, ph + 1, buf ^ 1);
        else load_B(c + 1, 0, buf ^ 1);
        if (ph == 0 && c + 1 < 16) load_A_halo(c + 1, ab ^ 1);
        asm volatile("cp.async.commit_group;");
        asm volatile("cp.async.wait_group 1;");
      } else {
        asm volatile("cp.async.wait_group 0;");
      }
      __syncthreads();

      const int tap = ph >> 1;
      const int bsel = ph & 1;
      const int dy = tap / 3;
      const int dxx = tap - dy * 3;
      const unsigned int tapoff = (unsigned)((dy * 18 + dxx) * (ASTR * 2));
      const unsigned int bb = bBase + buf * BBUF_B;

      unsigned int bf[4][4];
#pragma unroll
      for (int nf = 0; nf < 4; nf++)
        ldmatrix_x4(bf[nf][0], bf[nf][1], bf[nf][2], bf[nf][3],
                    bb + bfrag_off + (unsigned)(nf * 8 * (ASTR * 2)));

      const int npass = bsel ? 1 : 2;
#pragma unroll
      for (int pa = 0; pa < 2; pa++) {
        if (pa >= npass) break;
        const unsigned int ap =
            aBase + (unsigned)(ab * ABUF_B + (bsel ? 0 : pa) * PLANE_B) + tapoff;
#pragma unroll
        for (int ks = 0; ks < 2; ks++) {
          unsigned int a[4][4];
#pragma unroll
          for (int mf = 0; mf < 4; mf++)
            ldmatrix_x4(a[mf][0], a[mf][1], a[mf][2], a[mf][3],
                        ap + hb[mf] + (unsigned)(ks * 32));
#pragma unroll
          for (int mf = 0; mf < 4; mf++)
#pragma unroll
            for (int nf = 0; nf < 4; nf++) mma_16816(acc[mf][nf], a[mf], &bf[nf][ks * 2]);
        }
      }
      __syncthreads();
    }
  }

  // epilogue: acc/1024 + bias, relu -> g_x[oc][gy*200+gx]
  const float inv = 1.0f / 1024.0f;
#pragma unroll
  for (int mf = 0; mf < 4; mf++) {
    const int gy = y0 + wm * 4 + mf;
    const int c_lo = lane >> 2;
#pragma unroll
    for (int nf = 0; nf < 4; nf++) {
      const int ocb = oc0 + wn * 32 + nf * 8 + (lane & 3) * 2;
      const float bias0 = b1[ocb];
      const float bias1 = b1[ocb + 1];
      const int gxa = x0 + c_lo;
      const int gxb = gxa + 8;
      if (gxa < WW) {
        float v0 = acc[mf][nf][0] * inv + bias0;
        float v1 = acc[mf][nf][1] * inv + bias1;
        g_x[(size_t)ocb * NPIX + gy * WW + gxa] = v0 > 0.f ? v0 : 0.f;
        g_x[(size_t)(ocb + 1) * NPIX + gy * WW + gxa] = v1 > 0.f ? v1 : 0.f;
      }
      if (gxb < WW) {
        float v2 = acc[mf][nf][2] * inv + bias0;
        float v3 = acc[mf][nf][3] * inv + bias1;
        g_x[(size_t)ocb * NPIX + gy * WW + gxb] = v2 > 0.f ? v2 : 0.f;
        g_x[(size_t)(ocb + 1) * NPIX + gy * WW + gxb] = v3 > 0.f ? v3 : 0.f;
      }
    }
  }
}

// ---------------- head: fused 1x1 convs, 8-way oc split, 2 adjacent px per thread ----------------
__global__ __launch_bounds__(160) void head_kernel(
    const float* __restrict__ wc, const float* __restrict__ bc,
    const float* __restrict__ wl, const float* __restrict__ bl,
    float* __restrict__ out) {
  __shared__ __align__(16) float Ws[512][8];   // 7 used, padded to 8 for float4
  const int tid = threadIdx.x;
  const int px0 = blockIdx.x * 320;
  const int obase = blockIdx.y * 7;   // 8 groups of 7 (54 outputs)

  for (int idx = tid; idx < 512 * 8; idx += 160) {
    const int ic = idx >> 3;
    const int o = idx & 7;
    const int og = obase + o;
    float w = 0.f;
    if (o < 7 && og < 18) w = wc[og * 512 + ic];
    else if (o < 7 && og < 54) w = wl[(og - 18) * 512 + ic];
    Ws[ic][o] = w;
  }
  __syncthreads();

  const int pxA = px0 + 2 * tid;       // even, float2-aligned
  const int pxB = pxA + 1;
  float accA[7], accB[7];
#pragma unroll
  for (int o = 0; o < 7; o++) { accA[o] = 0.f; accB[o] = 0.f; }

#pragma unroll 4
  for (int ic = 0; ic < 512; ic++) {
    const float2 xv = *(const float2*)&g_x[(size_t)ic * NPIX + pxA];
    const float xa = xv.x;
    const float xb = xv.y;
    const float4* wrow = (const float4*)Ws[ic];
    const float4 w0 = wrow[0];
    const float4 w1 = wrow[1];
    accA[0] += w0.x * xa;  accA[1] += w0.y * xa;  accA[2] += w0.z * xa;  accA[3] += w0.w * xa;
    accA[4] += w1.x * xa;  accA[5] += w1.y * xa;  accA[6] += w1.z * xa;
    accB[0] += w0.x * xb;  accB[1] += w0.y * xb;  accB[2] += w0.z * xb;  accB[3] += w0.w * xb;
    accB[4] += w1.x * xb;  accB[5] += w1.y * xb;  accB[6] += w1.z * xb;
  }

#pragma unroll
  for (int o = 0; o < 7; o++) {
    const int og = obase + o;
    if (og < 18) {
      const int a = og >> 1, cc = og & 1;
      out[CLS_OFF + ((size_t)pxA * 9 + a) * 2 + cc] = accA[o] + bc[og];
      out[CLS_OFF + ((size_t)pxB * 9 + a) * 2 + cc] = accB[o] + bc[og];
    } else if (og < 54) {
      const int l = og - 18;
      const int a = l >> 2, cc = l & 3;
      out[LOC_OFF + ((size_t)pxA * 9 + a) * 4 + cc] = accA[o] + bl[l];
      out[LOC_OFF + ((size_t)pxB * 9 + a) * 4 + cc] = accB[o] + bl[l];
    }
  }
}

// ---------------- decode + score + sort key (vectorized loads/stores) ----------------
__global__ void decode_kernel(const float* __restrict__ anchor,
                              const float* __restrict__ out) {
  const int n = blockIdx.x * 256 + threadIdx.x;
  if (n >= NANCH) return;

  const float4 anc = ((const float4*)anchor)[n];
  const float ax1 = anc.x, ay1 = anc.y, ax2 = anc.z, ay2 = anc.w;
  const float acx = __fmul_rn(__fadd_rn(ax2, ax1), 0.5f);
  const float acy = __fmul_rn(__fadd_rn(ay2, ay1), 0.5f);
  const float aw = __fsub_rn(ax2, ax1);
  const float ah = __fsub_rn(ay2, ay1);

  const float4 locv = ((const float4*)(out + LOC_OFF))[n];
  const float l0 = locv.x, l1 = locv.y, l2 = locv.z, l3 = locv.w;

  const float cx = __fadd_rn(__fmul_rn(l0, aw), acx);
  const float cy = __fadd_rn(__fmul_rn(l1, ah), acy);
  const float w = __fmul_rn(expf(l2), aw);
  const float h = __fmul_rn(expf(l3), ah);

  float x1 = __fsub_rn(cx, __fmul_rn(w, 0.5f));
  float y1 = __fsub_rn(cy, __fmul_rn(h, 0.5f));
  float x2 = __fadd_rn(cx, __fmul_rn(w, 0.5f));
  float y2 = __fadd_rn(cy, __fmul_rn(h, 0.5f));
  x1 = fminf(fmaxf(x1, 0.f), 1.f);
  y1 = fminf(fmaxf(y1, 0.f), 1.f);
  x2 = fminf(fmaxf(x2, 0.f), 1.f);
  y2 = fminf(fmaxf(y2, 0.f), 1.f);

  float4 bx;
  bx.x = x1; bx.y = y1; bx.z = x2; bx.w = y2;
  ((float4*)g_boxes)[n] = bx;

  const float2 clsv = ((const float2*)(out + CLS_OFF))[n];
  float s = 1.f / (1.f + expf(__fsub_rn(clsv.x, clsv.y)));

  const float MINSZ = (float)(16.0 / 1000.0);
  const float ws = __fsub_rn(x2, x1);
  const float hs = __fsub_rn(y2, y1);
  const bool valid = (hs >= MINSZ) && (ws >= MINSZ);
  if (!valid) s = -1.0f;
  g_score[n] = s;

  unsigned int bits = __float_as_uint(s);
  unsigned int u = (bits & 0x80000000u) ? ~bits : (bits | 0x80000000u);
  // ascending radix sort of ~u -> descending score; CUB radix is stable, so
  // equal scores keep ascending index order (matches jax top_k tie rule).
  g_keys32[n] = ~u;
  g_vals32[n] = (unsigned int)n;
}

// ---------------- gather top 6000 + validity ballot (float4 copy) ----------------
__global__ void gather_kernel() {
  const int i = blockIdx.x * 256 + threadIdx.x;   // 24 blocks -> i < 6144
  int valid = 0;
  if (i < PRE_NMS) {
    const int idx = (int)g_vals32_s[i];
    ((float4*)g_top)[i] = ((const float4*)g_boxes)[idx];
    valid = (g_score[idx] >= 0.f) ? 1 : 0;
  }
  const unsigned int bal = __ballot_sync(0xffffffffu, valid);
  if ((threadIdx.x & 31) == 0) g_validw32[i >> 5] = bal;
}

// ---------------- NMS bitmask: paired column blocks (2 cb per block) ----------------
__global__ __launch_bounds__(64) void mask_kernel() {
  const int cb0 = blockIdx.x * 2;     // 47 x-blocks cover 94 cb
  const int rb = blockIdx.y;
  __shared__ float cbx[128][4];
  const int t = threadIdx.x;
#pragma unroll
  for (int half = 0; half < 2; half++) {
    const int jg = (cb0 + half) * 64 + t;
    if (jg < PRE_NMS) {
      const float4 b = ((const float4*)g_top)[jg];
      cbx[half * 64 + t][0] = b.x;
      cbx[half * 64 + t][1] = b.y;
      cbx[half * 64 + t][2] = b.z;
      cbx[half * 64 + t][3] = b.w;
    }
  }
  __syncthreads();
  const int i = rb * 64 + t;
  if (i >= PRE_NMS) return;

  const float4 bi = ((const float4*)g_top)[i];
  const float ix1 = bi.x, iy1 = bi.y, ix2 = bi.z, iy2 = bi.w;
  const float area_i = __fmul_rn(__fsub_rn(ix2, ix1), __fsub_rn(iy2, iy1));

#pragma unroll
  for (int half = 0; half < 2; half++) {
    const int cb = cb0 + half;
    unsigned long long bits = 0ull;
    const int jmax = min(64, PRE_NMS - cb * 64);
    for (int jj = 0; jj < jmax; jj++) {
      const int j = cb * 64 + jj;
      if (j <= i) continue;
      const int sj = half * 64 + jj;
      const float bx1 = cbx[sj][0], by1 = cbx[sj][1], bx2 = cbx[sj][2], by2 = cbx[sj][3];
      const float area_j = __fmul_rn(__fsub_rn(bx2, bx1), __fsub_rn(by2, by1));
      const float xx1 = fmaxf(ix1, bx1);
      const float yy1 = fmaxf(iy1, by1);
      const float xx2 = fminf(ix2, bx2);
      const float yy2 = fminf(iy2, by2);
      const float iw = fmaxf(__fsub_rn(xx2, xx1), 0.f);
      const float ih = fmaxf(__fsub_rn(yy2, yy1), 0.f);
      const float inter = __fmul_rn(iw, ih);
      const float denom = __fadd_rn(__fsub_rn(__fadd_rn(area_i, area_j), inter), 1e-12f);
      const float iou = inter / denom;
      if (iou > 0.7f) bits |= (1ull << jj);
    }
    g_mask[(size_t)i * NBLK + cb] = bits;
  }
}

// ---------------- sequential keep: word-at-a-time bit scan, early exit at 300 ----------------
__global__ void keep_kernel(float* __restrict__ out) {
  const int lane = threadIdx.x;
  unsigned long long r0 = 0ull, r1 = 0ull, r2 = 0ull;  // suppr words lane, +32, +64
  __shared__ unsigned long long validw[NBLK];
  __shared__ int kept_s[POST_NMS];

  for (int w = lane; w < NBLK; w += 32) {
    const unsigned int lo = g_validw32[2 * w];
    const unsigned int hi = (2 * w + 1 < 192) ? g_validw32[2 * w + 1] : 0u;
    validw[w] = (unsigned long long)lo | ((unsigned long long)hi << 32);
  }
  __syncwarp();

  int count = 0;
  for (int w = 0; w < NBLK && count < POST_NMS; w++) {
    const int slot = w >> 5;
    const int src = w & 31;
    unsigned long long v = (slot == 0) ? r0 : ((slot == 1) ? r1 : r2);
    unsigned long long sup = __shfl_sync(0xffffffffu, v, src);
    unsigned long long cand = validw[w] & ~sup;
    while (cand && count < POST_NMS) {
      const int b = __ffsll((long long)cand) - 1;
      const int i = w * 64 + b;
      if (lane == 0) kept_s[count] = i;
      count++;
      const unsigned long long* row = &g_mask[(size_t)i * NBLK];
      r0 |= row[lane];
      r1 |= row[lane + 32];
      if (lane + 64 < NBLK) r2 |= row[lane + 64];
      if (i + 1 < PRE_NMS) {
        const unsigned long long* nr = &g_mask[(size_t)(i + 1) * NBLK];
        asm volatile("prefetch.global.L1 [%0];" :: "l"(nr + lane));
        asm volatile("prefetch.global.L1 [%0];" :: "l"(nr + lane + 32));
      }
      if (i + 2 < PRE_NMS) {
        const unsigned long long* nr = &g_mask[(size_t)(i + 2) * NBLK];
        asm volatile("prefetch.global.L1 [%0];" :: "l"(nr + lane));
        asm volatile("prefetch.global.L1 [%0];" :: "l"(nr + lane + 32));
      }
      v = (slot == 0) ? r0 : ((slot == 1) ? r1 : r2);
      sup = __shfl_sync(0xffffffffu, v, src);
      const unsigned long long above = (b == 63) ? 0ull : (~0ull << (b + 1));
      cand = validw[w] & ~sup & above;
    }
  }
  __syncwarp();

  for (int k = lane; k < POST_NMS; k += 32) {
    float b0 = 0.f, b1v = 0.f, b2 = 0.f, b3 = 0.f;
    if (k < count) {
      const int i = kept_s[k];
      b0 = g_top[i * 4 + 0];
      b1v = g_top[i * 4 + 1];
      b2 = g_top[i * 4 + 2];
      b3 = g_top[i * 4 + 3];
    }
    out[ROI_OFF + k * 4 + 0] = b0;
    out[ROI_OFF + k * 4 + 1] = b1v;
    out[ROI_OFF + k * 4 + 2] = b2;
    out[ROI_OFF + k * 4 + 3] = b3;
  }
}

// ---------------- launch ----------------
extern "C" void kernel_launch(void* const* d_in, const int* in_sizes, int n_in,
                              void* d_out, int out_size) {
  const float* feat = (const float*)d_in[0];
  const float* anchor = (const float*)d_in[1];
  const float* w1 = (const float*)d_in[2];
  const float* b1 = (const float*)d_in[3];
  const float* wc = (const float*)d_in[4];
  const float* bc = (const float*)d_in[5];
  const float* wl = (const float*)d_in[6];
  const float* bl = (const float*)d_in[7];
  float* out = (float*)d_out;

  split_feat_kernel<<<dim3(1250, 16), dim3(32, 8)>>>(feat);
  split_w_kernel<<<(512 * 512 + 255) / 256, 256>>>(w1);

  cudaFuncSetAttribute(conv1_mma_kernel,
                       cudaFuncAttributeMaxDynamicSharedMemorySize, CONV_SMEM);
  conv1_mma_kernel<<<dim3(4, 13, 25), 256, CONV_SMEM>>>(b1);

  head_kernel<<<dim3(125, 8), 160>>>(wc, bc, wl, bl, out);
  decode_kernel<<<(NANCH + 255) / 256, 256>>>(anchor, out);

  // CUB stable radix SortPairs on 32-bit keys
  void* d_temp = nullptr;
  unsigned int *dk, *dks, *dv, *dvs;
  cudaGetSymbolAddress(&d_temp, g_cub_temp);
  cudaGetSymbolAddress((void**)&dk, g_keys32);
  cudaGetSymbolAddress((void**)&dks, g_keys32_s);
  cudaGetSymbolAddress((void**)&dv, g_vals32);
  cudaGetSymbolAddress((void**)&dvs, g_vals32_s);
  size_t temp_bytes = 0;
  cub::DeviceRadixSort::SortPairs(nullptr, temp_bytes, dk, dks, dv, dvs, NANCH,
                                  0, 32, (cudaStream_t)0);
  if (temp_bytes > (size_t)(64u << 20)) temp_bytes = (size_t)(64u << 20);
  cub::DeviceRadixSort::SortPairs(d_temp, temp_bytes, dk, dks, dv, dvs, NANCH,
                                  0, 32, (cudaStream_t)0);

  gather_kernel<<<24, 256>>>();
  mask_kernel<<<dim3(47, NBLK), 64>>>();
  keep_kernel<<<1, 32>>>(out);
}

// round 17
// speedup vs baseline: 1.0295x; 1.0004x over previous
#include <cuda_runtime.h>
#include <cuda_fp16.h>
#include <cuda_bf16.h>
#include <cstdint>
#include <cub/cub.cuh>

// ---------------- problem constants ----------------
#define HH 200
#define WW 200
#define NPIX (HH * WW)          // 40000
#define NANCH 360000            // HH*WW*9
#define PRE_NMS 6000
#define POST_NMS 300
#define NBLK 94                 // ceil(6000/64)
#define CLS_OFF 0
#define LOC_OFF 720000
#define ROI_OFF 2160000

#define ASTR 40                 // smem row stride in halves (32 + 8 pad)
#define HROWS 180               // 10 x 18 halo rows
#define PLANE_H (HROWS * ASTR)  // halves per A plane (7200)
#define PLANE_B (PLANE_H * 2)   // bytes per A plane (14400)
#define ABUF_B (2 * PLANE_B)    // bytes per A buffer, both planes (28800)
#define BROWS 128
#define BBUF_B (BROWS * ASTR * 2)           // bytes per B buffer (10240)
#define CONV_SMEM (2 * ABUF_B + 2 * BBUF_B) // 78080 bytes dynamic smem

// ---------------- scratch (static device allocations) ----------------
__device__ float g_x[512 * NPIX];                 // relu(conv1) output, [oc][px]
__device__ __half g_ah[(size_t)NPIX * 512];       // features transposed [px][ic], high half
__device__ __half g_am[(size_t)NPIX * 512];       // low half
__device__ __half g_wh[(size_t)9 * 512 * 512];    // weights [tap][oc][ic], high half (x1024)
__device__ __half g_wm[(size_t)9 * 512 * 512];    // low half (x1024)
__device__ float g_boxes[NANCH * 4];
__device__ float g_score[NANCH];
__device__ unsigned int g_keys32[NANCH];
__device__ unsigned int g_vals32[NANCH];
__device__ unsigned int g_keys32_s[NANCH];
__device__ unsigned int g_vals32_s[NANCH];
__device__ float g_top[PRE_NMS * 4];
__device__ unsigned int g_validw32[192];          // validity bitmask (6144 bits)
__device__ unsigned long long g_mask[(size_t)PRE_NMS * NBLK];
__device__ unsigned char g_cub_temp[64u << 20];

// ---------------- small PTX helpers ----------------
__device__ __forceinline__ unsigned int smem_u32(const void* p) {
  unsigned int a;
  asm("{ .reg .u64 t; cvta.to.shared.u64 t, %1; cvt.u32.u64 %0, t; }" : "=r"(a) : "l"(p));
  return a;
}
__device__ __forceinline__ void cp_async16(unsigned int saddr, const void* gptr,
                                           unsigned int srcsize) {
  asm volatile("cp.async.cg.shared.global [%0], [%1], 16, %2;"
               :: "r"(saddr), "l"(gptr), "r"(srcsize));
}
__device__ __forceinline__ void ldmatrix_x4(unsigned int& r0, unsigned int& r1,
                                            unsigned int& r2, unsigned int& r3,
                                            unsigned int addr) {
  asm volatile("ldmatrix.sync.aligned.m8n8.x4.shared.b16 {%0,%1,%2,%3}, [%4];"
               : "=r"(r0), "=r"(r1), "=r"(r2), "=r"(r3) : "r"(addr));
}
__device__ __forceinline__ void mma_16816(float* c, const unsigned int* a,
                                          const unsigned int* b) {
  asm volatile(
      "mma.sync.aligned.m16n8k16.row.col.f32.f16.f16.f32 "
      "{%0,%1,%2,%3}, {%4,%5,%6,%7}, {%8,%9}, {%0,%1,%2,%3};"
      : "+f"(c[0]), "+f"(c[1]), "+f"(c[2]), "+f"(c[3])
      : "r"(a[0]), "r"(a[1]), "r"(a[2]), "r"(a[3]), "r"(b[0]), "r"(b[1]));
}

// ---------------- dummy (profiler slot alignment) ----------------
__global__ void dummy_kernel() {}

// ---------------- pre: merged feature split + weight split ----------------
// Grid (1250, 17), block (32,8). Rows y<16: feature transpose+split (as before,
// bit-identical). Row y==16: weight split for blocks x<1024 (i = x*256+tid).
__global__ __launch_bounds__(256) void split_all_kernel(
    const float* __restrict__ feat, const float* __restrict__ w1) {
  const int tx = threadIdx.x;
  const int ty = threadIdx.y;
  const int tid = ty * 32 + tx;

  if (blockIdx.y == 16) {
    if (blockIdx.x >= 1024) return;
    const int i = blockIdx.x * 256 + tid;  // oc*512 + ic, i < 262144
#pragma unroll
    for (int t = 0; t < 9; t++) {
      const float w = w1[(size_t)i * 9 + t] * 1024.0f;
      const __half h = __float2half(w);
      const __half m = __float2half(w - __half2float(h));
      g_wh[(size_t)t * 262144 + i] = h;
      g_wm[(size_t)t * 262144 + i] = m;
    }
    return;
  }

  __shared__ float tile[32][33];
  const int pxb = blockIdx.x * 32;
  const int icb = blockIdx.y * 32;
#pragma unroll
  for (int r = 0; r < 4; r++)
    tile[ty + r * 8][tx] = feat[(size_t)(icb + ty + r * 8) * NPIX + pxb + tx];
  __syncthreads();
#pragma unroll
  for (int it = 0; it < 2; it++) {
    const int item = it * 256 + tid;
    const int p = item & 15;          // ic pair index
    const int pxl = item >> 4;        // px row 0..31
    const float v0 = tile[2 * p][pxl];
    const float v1 = tile[2 * p + 1][pxl];
    const __half h0 = __float2half(v0);
    const __half m0 = __float2half(v0 - __half2float(h0));
    const __half h1 = __float2half(v1);
    const __half m1 = __float2half(v1 - __half2float(h1));
    const size_t base = ((size_t)(pxb + pxl) * 512 + icb + 2 * p) >> 1;
    ((unsigned int*)g_ah)[base] =
        (unsigned int)__half_as_ushort(h0) | ((unsigned int)__half_as_ushort(h1) << 16);
    ((unsigned int*)g_am)[base] =
        (unsigned int)__half_as_ushort(m0) | ((unsigned int)__half_as_ushort(m1) << 16);
  }
}

// ---------------- conv1 via mma.sync: spatial 16x8 px tile x 128 oc ----------------
// R16 config (FROZEN): two syncs per phase, double-buffered B, double-buffered
// A halo (chunk c+1 halo prefetched during chunk c phase 0).
__global__ __launch_bounds__(256) void conv1_mma_kernel(const float* __restrict__ b1) {
  extern __shared__ __align__(16) unsigned char dynsmem[];
  const unsigned int aBase = smem_u32(dynsmem);              // 2 abuf x 2 planes
  const unsigned int bBase = aBase + 2 * ABUF_B;             // 2 B buffers

  const int tid = threadIdx.x;
  const int lane = tid & 31;
  const int wid = tid >> 5;
  const int wm = wid & 1;          // px half (64 px)
  const int wn = wid >> 1;         // oc quarter (32 oc)

  const int oc0 = blockIdx.x * 128;
  const int x0 = blockIdx.y * 16;  // 13 x-tiles
  const int y0 = blockIdx.z * 8;   // 25 y-tiles

  unsigned int hb[4];
#pragma unroll
  for (int mf = 0; mf < 4; mf++)
    hb[mf] = (unsigned)(((wm * 4 + mf) * 18 + (lane & 15)) * (ASTR * 2) + (lane >> 4) * 16);
  const unsigned int bfrag_off =
      (unsigned)((wn * 32 + (lane & 7)) * (ASTR * 2) + (lane >> 3) * 16);

  float acc[4][4][4];
#pragma unroll
  for (int mf = 0; mf < 4; mf++)
#pragma unroll
    for (int nf = 0; nf < 4; nf++)
#pragma unroll
      for (int q = 0; q < 4; q++) acc[mf][nf][q] = 0.f;

  auto load_A_halo = [&](int c, int abuf) {
    for (int idx = tid; idx < 1440; idx += 256) {
      const int pl = idx / 720;
      const int rr = idx - pl * 720;
      const int hrow = rr >> 2;
      const int seg = rr & 3;
      const int hr = hrow / 18;
      const int hc = hrow - hr * 18;
      const int gy = y0 + hr - 1;
      const int gx = x0 + hc - 1;
      const bool ok = ((unsigned)gy < (unsigned)HH) && ((unsigned)gx < (unsigned)WW);
      const int gpx = ok ? (gy * WW + gx) : 0;
      const __half* src = (pl ? g_am : g_ah) + (size_t)gpx * 512 + c * 32 + seg * 8;
      cp_async16(aBase + (unsigned)(abuf * ABUF_B + pl * PLANE_B + hrow * (ASTR * 2) + seg * 16),
                 src, ok ? 16u : 0u);
    }
  };
  auto load_B = [&](int c, int ph, int buf) {
    const int tap = ph >> 1;
    const int bsel = ph & 1;
    const __half* plane = (bsel ? g_wm : g_wh) + (size_t)tap * 262144;
    for (int idx = tid; idx < 512; idx += 256) {
      const int row = idx >> 2;
      const int seg = idx & 3;
      const __half* src = plane + (size_t)(oc0 + row) * 512 + c * 32 + seg * 8;
      cp_async16(bBase + (unsigned)(buf * BBUF_B + row * (ASTR * 2) + seg * 16), src,
                 16u);
    }
  };

  // prologue: chunk 0 halo + first B tile, full drain once
  load_A_halo(0, 0);
  load_B(0, 0, 0);
  asm volatile("cp.async.commit_group;");
  asm volatile("cp.async.wait_group 0;");
  __syncthreads();

  for (int c = 0; c < 16; c++) {
    const int ab = c & 1;
    for (int ph = 0; ph < 18; ph++) {
      const int buf = ph & 1;
      const bool last = (c == 15) && (ph == 17);
      if (!last) {
        if (ph + 1 < 18) load_B(c, ph + 1, buf ^ 1);
        else load_B(c + 1, 0, buf ^ 1);
        if (ph == 0 && c + 1 < 16) load_A_halo(c + 1, ab ^ 1);
        asm volatile("cp.async.commit_group;");
        asm volatile("cp.async.wait_group 1;");
      } else {
        asm volatile("cp.async.wait_group 0;");
      }
      __syncthreads();

      const int tap = ph >> 1;
      const int bsel = ph & 1;
      const int dy = tap / 3;
      const int dxx = tap - dy * 3;
      const unsigned int tapoff = (unsigned)((dy * 18 + dxx) * (ASTR * 2));
      const unsigned int bb = bBase + buf * BBUF_B;

      unsigned int bf[4][4];
#pragma unroll
      for (int nf = 0; nf < 4; nf++)
        ldmatrix_x4(bf[nf][0], bf[nf][1], bf[nf][2], bf[nf][3],
                    bb + bfrag_off + (unsigned)(nf * 8 * (ASTR * 2)));

      const int npass = bsel ? 1 : 2;
#pragma unroll
      for (int pa = 0; pa < 2; pa++) {
        if (pa >= npass) break;
        const unsigned int ap =
            aBase + (unsigned)(ab * ABUF_B + (bsel ? 0 : pa) * PLANE_B) + tapoff;
#pragma unroll
        for (int ks = 0; ks < 2; ks++) {
          unsigned int a[4][4];
#pragma unroll
          for (int mf = 0; mf < 4; mf++)
            ldmatrix_x4(a[mf][0], a[mf][1], a[mf][2], a[mf][3],
                        ap + hb[mf] + (unsigned)(ks * 32));
#pragma unroll
          for (int mf = 0; mf < 4; mf++)
#pragma unroll
            for (int nf = 0; nf < 4; nf++) mma_16816(acc[mf][nf], a[mf], &bf[nf][ks * 2]);
        }
      }
      __syncthreads();
    }
  }

  // epilogue: acc/1024 + bias, relu -> g_x[oc][gy*200+gx]
  const float inv = 1.0f / 1024.0f;
#pragma unroll
  for (int mf = 0; mf < 4; mf++) {
    const int gy = y0 + wm * 4 + mf;
    const int c_lo = lane >> 2;
#pragma unroll
    for (int nf = 0; nf < 4; nf++) {
      const int ocb = oc0 + wn * 32 + nf * 8 + (lane & 3) * 2;
      const float bias0 = b1[ocb];
      const float bias1 = b1[ocb + 1];
      const int gxa = x0 + c_lo;
      const int gxb = gxa + 8;
      if (gxa < WW) {
        float v0 = acc[mf][nf][0] * inv + bias0;
        float v1 = acc[mf][nf][1] * inv + bias1;
        g_x[(size_t)ocb * NPIX + gy * WW + gxa] = v0 > 0.f ? v0 : 0.f;
        g_x[(size_t)(ocb + 1) * NPIX + gy * WW + gxa] = v1 > 0.f ? v1 : 0.f;
      }
      if (gxb < WW) {
        float v2 = acc[mf][nf][2] * inv + bias0;
        float v3 = acc[mf][nf][3] * inv + bias1;
        g_x[(size_t)ocb * NPIX + gy * WW + gxb] = v2 > 0.f ? v2 : 0.f;
        g_x[(size_t)(ocb + 1) * NPIX + gy * WW + gxb] = v3 > 0.f ? v3 : 0.f;
      }
    }
  }
}

// ---------------- head: fused 1x1 convs, 8-way oc split, 2 adjacent px per thread ----------------
__global__ __launch_bounds__(160) void head_kernel(
    const float* __restrict__ wc, const float* __restrict__ bc,
    const float* __restrict__ wl, const float* __restrict__ bl,
    float* __restrict__ out) {
  __shared__ __align__(16) float Ws[512][8];   // 7 used, padded to 8 for float4
  const int tid = threadIdx.x;
  const int px0 = blockIdx.x * 320;
  const int obase = blockIdx.y * 7;   // 8 groups of 7 (54 outputs)

  for (int idx = tid; idx < 512 * 8; idx += 160) {
    const int ic = idx >> 3;
    const int o = idx & 7;
    const int og = obase + o;
    float w = 0.f;
    if (o < 7 && og < 18) w = wc[og * 512 + ic];
    else if (o < 7 && og < 54) w = wl[(og - 18) * 512 + ic];
    Ws[ic][o] = w;
  }
  __syncthreads();

  const int pxA = px0 + 2 * tid;       // even, float2-aligned
  const int pxB = pxA + 1;
  float accA[7], accB[7];
#pragma unroll
  for (int o = 0; o < 7; o++) { accA[o] = 0.f; accB[o] = 0.f; }

#pragma unroll 4
  for (int ic = 0; ic < 512; ic++) {
    const float2 xv = *(const float2*)&g_x[(size_t)ic * NPIX + pxA];
    const float xa = xv.x;
    const float xb = xv.y;
    const float4* wrow = (const float4*)Ws[ic];
    const float4 w0 = wrow[0];
    const float4 w1 = wrow[1];
    accA[0] += w0.x * xa;  accA[1] += w0.y * xa;  accA[2] += w0.z * xa;  accA[3] += w0.w * xa;
    accA[4] += w1.x * xa;  accA[5] += w1.y * xa;  accA[6] += w1.z * xa;
    accB[0] += w0.x * xb;  accB[1] += w0.y * xb;  accB[2] += w0.z * xb;  accB[3] += w0.w * xb;
    accB[4] += w1.x * xb;  accB[5] += w1.y * xb;  accB[6] += w1.z * xb;
  }

#pragma unroll
  for (int o = 0; o < 7; o++) {
    const int og = obase + o;
    if (og < 18) {
      const int a = og >> 1, cc = og & 1;
      out[CLS_OFF + ((size_t)pxA * 9 + a) * 2 + cc] = accA[o] + bc[og];
      out[CLS_OFF + ((size_t)pxB * 9 + a) * 2 + cc] = accB[o] + bc[og];
    } else if (og < 54) {
      const int l = og - 18;
      const int a = l >> 2, cc = l & 3;
      out[LOC_OFF + ((size_t)pxA * 9 + a) * 4 + cc] = accA[o] + bl[l];
      out[LOC_OFF + ((size_t)pxB * 9 + a) * 4 + cc] = accB[o] + bl[l];
    }
  }
}

// ---------------- decode + score + sort key (vectorized loads/stores) ----------------
__global__ void decode_kernel(const float* __restrict__ anchor,
                              const float* __restrict__ out) {
  const int n = blockIdx.x * 256 + threadIdx.x;
  if (n >= NANCH) return;

  const float4 anc = ((const float4*)anchor)[n];
  const float ax1 = anc.x, ay1 = anc.y, ax2 = anc.z, ay2 = anc.w;
  const float acx = __fmul_rn(__fadd_rn(ax2, ax1), 0.5f);
  const float acy = __fmul_rn(__fadd_rn(ay2, ay1), 0.5f);
  const float aw = __fsub_rn(ax2, ax1);
  const float ah = __fsub_rn(ay2, ay1);

  const float4 locv = ((const float4*)(out + LOC_OFF))[n];
  const float l0 = locv.x, l1 = locv.y, l2 = locv.z, l3 = locv.w;

  const float cx = __fadd_rn(__fmul_rn(l0, aw), acx);
  const float cy = __fadd_rn(__fmul_rn(l1, ah), acy);
  const float w = __fmul_rn(expf(l2), aw);
  const float h = __fmul_rn(expf(l3), ah);

  float x1 = __fsub_rn(cx, __fmul_rn(w, 0.5f));
  float y1 = __fsub_rn(cy, __fmul_rn(h, 0.5f));
  float x2 = __fadd_rn(cx, __fmul_rn(w, 0.5f));
  float y2 = __fadd_rn(cy, __fmul_rn(h, 0.5f));
  x1 = fminf(fmaxf(x1, 0.f), 1.f);
  y1 = fminf(fmaxf(y1, 0.f), 1.f);
  x2 = fminf(fmaxf(x2, 0.f), 1.f);
  y2 = fminf(fmaxf(y2, 0.f), 1.f);

  float4 bx;
  bx.x = x1; bx.y = y1; bx.z = x2; bx.w = y2;
  ((float4*)g_boxes)[n] = bx;

  const float2 clsv = ((const float2*)(out + CLS_OFF))[n];
  float s = 1.f / (1.f + expf(__fsub_rn(clsv.x, clsv.y)));

  const float MINSZ = (float)(16.0 / 1000.0);
  const float ws = __fsub_rn(x2, x1);
  const float hs = __fsub_rn(y2, y1);
  const bool valid = (hs >= MINSZ) && (ws >= MINSZ);
  if (!valid) s = -1.0f;
  g_score[n] = s;

  unsigned int bits = __float_as_uint(s);
  unsigned int u = (bits & 0x80000000u) ? ~bits : (bits | 0x80000000u);
  // ascending radix sort of ~u -> descending score; CUB radix is stable, so
  // equal scores keep ascending index order (matches jax top_k tie rule).
  g_keys32[n] = ~u;
  g_vals32[n] = (unsigned int)n;
}

// ---------------- gather top 6000 + validity ballot (float4 copy) ----------------
__global__ void gather_kernel() {
  const int i = blockIdx.x * 256 + threadIdx.x;   // 24 blocks -> i < 6144
  int valid = 0;
  if (i < PRE_NMS) {
    const int idx = (int)g_vals32_s[i];
    ((float4*)g_top)[i] = ((const float4*)g_boxes)[idx];
    valid = (g_score[idx] >= 0.f) ? 1 : 0;
  }
  const unsigned int bal = __ballot_sync(0xffffffffu, valid);
  if ((threadIdx.x & 31) == 0) g_validw32[i >> 5] = bal;
}

// ---------------- NMS bitmask: paired column blocks (2 cb per block) ----------------
__global__ __launch_bounds__(64) void mask_kernel() {
  const int cb0 = blockIdx.x * 2;     // 47 x-blocks cover 94 cb
  const int rb = blockIdx.y;
  __shared__ float cbx[128][4];
  const int t = threadIdx.x;
#pragma unroll
  for (int half = 0; half < 2; half++) {
    const int jg = (cb0 + half) * 64 + t;
    if (jg < PRE_NMS) {
      const float4 b = ((const float4*)g_top)[jg];
      cbx[half * 64 + t][0] = b.x;
      cbx[half * 64 + t][1] = b.y;
      cbx[half * 64 + t][2] = b.z;
      cbx[half * 64 + t][3] = b.w;
    }
  }
  __syncthreads();
  const int i = rb * 64 + t;
  if (i >= PRE_NMS) return;

  const float4 bi = ((const float4*)g_top)[i];
  const float ix1 = bi.x, iy1 = bi.y, ix2 = bi.z, iy2 = bi.w;
  const float area_i = __fmul_rn(__fsub_rn(ix2, ix1), __fsub_rn(iy2, iy1));

#pragma unroll
  for (int half = 0; half < 2; half++) {
    const int cb = cb0 + half;
    unsigned long long bits = 0ull;
    const int jmax = min(64, PRE_NMS - cb * 64);
    for (int jj = 0; jj < jmax; jj++) {
      const int j = cb * 64 + jj;
      if (j <= i) continue;
      const int sj = half * 64 + jj;
      const float bx1 = cbx[sj][0], by1 = cbx[sj][1], bx2 = cbx[sj][2], by2 = cbx[sj][3];
      const float area_j = __fmul_rn(__fsub_rn(bx2, bx1), __fsub_rn(by2, by1));
      const float xx1 = fmaxf(ix1, bx1);
      const float yy1 = fmaxf(iy1, by1);
      const float xx2 = fminf(ix2, bx2);
      const float yy2 = fminf(iy2, by2);
      const float iw = fmaxf(__fsub_rn(xx2, xx1), 0.f);
      const float ih = fmaxf(__fsub_rn(yy2, yy1), 0.f);
      const float inter = __fmul_rn(iw, ih);
      const float denom = __fadd_rn(__fsub_rn(__fadd_rn(area_i, area_j), inter), 1e-12f);
      const float iou = inter / denom;
      if (iou > 0.7f) bits |= (1ull << jj);
    }
    g_mask[(size_t)i * NBLK + cb] = bits;
  }
}

// ---------------- sequential keep: word-at-a-time bit scan, early exit at 300 ----------------
__global__ void keep_kernel(float* __restrict__ out) {
  const int lane = threadIdx.x;
  unsigned long long r0 = 0ull, r1 = 0ull, r2 = 0ull;  // suppr words lane, +32, +64
  __shared__ unsigned long long validw[NBLK];
  __shared__ int kept_s[POST_NMS];

  for (int w = lane; w < NBLK; w += 32) {
    const unsigned int lo = g_validw32[2 * w];
    const unsigned int hi = (2 * w + 1 < 192) ? g_validw32[2 * w + 1] : 0u;
    validw[w] = (unsigned long long)lo | ((unsigned long long)hi << 32);
  }
  __syncwarp();

  int count = 0;
  for (int w = 0; w < NBLK && count < POST_NMS; w++) {
    const int slot = w >> 5;
    const int src = w & 31;
    unsigned long long v = (slot == 0) ? r0 : ((slot == 1) ? r1 : r2);
    unsigned long long sup = __shfl_sync(0xffffffffu, v, src);
    unsigned long long cand = validw[w] & ~sup;
    while (cand && count < POST_NMS) {
      const int b = __ffsll((long long)cand) - 1;
      const int i = w * 64 + b;
      if (lane == 0) kept_s[count] = i;
      count++;
      const unsigned long long* row = &g_mask[(size_t)i * NBLK];
      r0 |= row[lane];
      r1 |= row[lane + 32];
      if (lane + 64 < NBLK) r2 |= row[lane + 64];
      if (i + 1 < PRE_NMS) {
        const unsigned long long* nr = &g_mask[(size_t)(i + 1) * NBLK];
        asm volatile("prefetch.global.L1 [%0];" :: "l"(nr + lane));
        asm volatile("prefetch.global.L1 [%0];" :: "l"(nr + lane + 32));
      }
      if (i + 2 < PRE_NMS) {
        const unsigned long long* nr = &g_mask[(size_t)(i + 2) * NBLK];
        asm volatile("prefetch.global.L1 [%0];" :: "l"(nr + lane));
        asm volatile("prefetch.global.L1 [%0];" :: "l"(nr + lane + 32));
      }
      v = (slot == 0) ? r0 : ((slot == 1) ? r1 : r2);
      sup = __shfl_sync(0xffffffffu, v, src);
      const unsigned long long above = (b == 63) ? 0ull : (~0ull << (b + 1));
      cand = validw[w] & ~sup & above;
    }
  }
  __syncwarp();

  for (int k = lane; k < POST_NMS; k += 32) {
    float b0 = 0.f, b1v = 0.f, b2 = 0.f, b3 = 0.f;
    if (k < count) {
      const int i = kept_s[k];
      b0 = g_top[i * 4 + 0];
      b1v = g_top[i * 4 + 1];
      b2 = g_top[i * 4 + 2];
      b3 = g_top[i * 4 + 3];
    }
    out[ROI_OFF + k * 4 + 0] = b0;
    out[ROI_OFF + k * 4 + 1] = b1v;
    out[ROI_OFF + k * 4 + 2] = b2;
    out[ROI_OFF + k * 4 + 3] = b3;
  }
}

// ---------------- launch ----------------
extern "C" void kernel_launch(void* const* d_in, const int* in_sizes, int n_in,
                              void* d_out, int out_size) {
  const float* feat = (const float*)d_in[0];
  const float* anchor = (const float*)d_in[1];
  const float* w1 = (const float*)d_in[2];
  const float* b1 = (const float*)d_in[3];
  const float* wc = (const float*)d_in[4];
  const float* bc = (const float*)d_in[5];
  const float* wl = (const float*)d_in[6];
  const float* bl = (const float*)d_in[7];
  float* out = (float*)d_out;

  // merged splits (launch #1), then two no-op kernels so conv sits in the
  // profiler's capture slot (#4) -- instrumentation for the conv roofline.
  split_all_kernel<<<dim3(1250, 17), dim3(32, 8)>>>(feat, w1);
  dummy_kernel<<<1, 1>>>();
  dummy_kernel<<<1, 1>>>();

  cudaFuncSetAttribute(conv1_mma_kernel,
                       cudaFuncAttributeMaxDynamicSharedMemorySize, CONV_SMEM);
  conv1_mma_kernel<<<dim3(4, 13, 25), 256, CONV_SMEM>>>(b1);

  head_kernel<<<dim3(125, 8), 160>>>(wc, bc, wl, bl, out);
  decode_kernel<<<(NANCH + 255) / 256, 256>>>(anchor, out);

  // CUB stable radix SortPairs on 32-bit keys
  void* d_temp = nullptr;
  unsigned int *dk, *dks, *dv, *dvs;
  cudaGetSymbolAddress(&d_temp, g_cub_temp);
  cudaGetSymbolAddress((void**)&dk, g_keys32);
  cudaGetSymbolAddress((void**)&dks, g_keys32_s);
  cudaGetSymbolAddress((void**)&dv, g_vals32);
  cudaGetSymbolAddress((void**)&dvs, g_vals32_s);
  size_t temp_bytes = 0;
  cub::DeviceRadixSort::SortPairs(nullptr, temp_bytes, dk, dks, dv, dvs, NANCH,
                                  0, 32, (cudaStream_t)0);
  if (temp_bytes > (size_t)(64u << 20)) temp_bytes = (size_t)(64u << 20);
  cub::DeviceRadixSort::SortPairs(d_temp, temp_bytes, dk, dks, dv, dvs, NANCH,
                                  0, 32, (cudaStream_t)0);

  gather_kernel<<<24, 256>>>();
  mask_kernel<<<dim3(47, NBLK), 64>>>();
  keep_kernel<<<1, 32>>>(out);
}